// round 6
// baseline (speedup 1.0000x reference)
#include <cuda_runtime.h>
#include <cuda_fp16.h>
#include <cstdint>

// Problem dims
#define B_BATCH   128
#define T_SEQ     2048
#define K_DIM     128    // J (softmax / contraction dim)
#define N_DIM     512    // d (output feature dim)
#define M_TILE    128
#define N_HALF    256    // each CTA owns one 256-col half of N
#define NCHUNK    128    // register chunks of 128 cols
#define NCHUNKS   2
#define THREADS   256

#define A_PITCH_B 272    // bytes per A row (136 fp16; +8 pad -> conflict-free ldsm)
#define B_PITCH_B 528    // bytes per B row (264 fp16; +8 pad -> conflict-free ldsm.trans)
#define A_BYTES   (128 * A_PITCH_B)     // 34,816
#define B_BYTES   (128 * B_PITCH_B)     // 67,584
static constexpr unsigned SMEM_TOTAL = A_BYTES + B_BYTES;  // 102,400 B -> 2 CTAs/SM

// ---------------- helpers ----------------
static __device__ __forceinline__ uint32_t smem_u32(const void* p) {
    uint32_t a;
    asm("{ .reg .u64 t; cvta.to.shared.u64 t, %1; cvt.u32.u64 %0, t; }" : "=r"(a) : "l"(p));
    return a;
}

// pack two f32 -> f16x2 (lo = x, hi = y)
static __device__ __forceinline__ uint32_t pack_f16x2(float x, float y) {
    uint32_t r;
    asm("cvt.rn.f16x2.f32 %0, %1, %2;" : "=r"(r) : "f"(y), "f"(x));
    return r;
}

static __device__ __forceinline__ void ldsm_x4(
    uint32_t& r0, uint32_t& r1, uint32_t& r2, uint32_t& r3, uint32_t addr)
{
    asm volatile("ldmatrix.sync.aligned.m8n8.x4.shared.b16 {%0,%1,%2,%3}, [%4];"
                 : "=r"(r0), "=r"(r1), "=r"(r2), "=r"(r3) : "r"(addr));
}

static __device__ __forceinline__ void ldsm_x4_trans(
    uint32_t& r0, uint32_t& r1, uint32_t& r2, uint32_t& r3, uint32_t addr)
{
    asm volatile("ldmatrix.sync.aligned.m8n8.x4.trans.shared.b16 {%0,%1,%2,%3}, [%4];"
                 : "=r"(r0), "=r"(r1), "=r"(r2), "=r"(r3) : "r"(addr));
}

static __device__ __forceinline__ void mma_f16(
    float& c0, float& c1, float& c2, float& c3,
    uint32_t a0, uint32_t a1, uint32_t a2, uint32_t a3,
    uint32_t b0, uint32_t b1)
{
    asm volatile(
        "mma.sync.aligned.m16n8k16.row.col.f32.f16.f16.f32 "
        "{%0,%1,%2,%3}, {%4,%5,%6,%7}, {%8,%9}, {%0,%1,%2,%3};"
        : "+f"(c0), "+f"(c1), "+f"(c2), "+f"(c3)
        : "r"(a0), "r"(a1), "r"(a2), "r"(a3), "r"(b0), "r"(b1));
}

// ---------------- kernel ----------------
// Grid: (16 M-tiles, 2 N-halves, 128 batches). 256 threads = 8 warps. 2 CTAs/SM.
// Each CTA: resident fp16 B half [K=128][256(+pad)], fused softmax -> fp16 A.
// Warp layout per chunk: warpM = wid&1 (2 x 64 rows), warpN = wid>>1 (4 x 32 cols).
__global__ void __launch_bounds__(THREADS, 2)
C2Q_15032385536516_kernel(const float* __restrict__ U,
                          const float* __restrict__ S,
                          float* __restrict__ Out)
{
    extern __shared__ char smem[];
    const uint32_t sA = smem_u32(smem);           // A: fp16 probs [128][136]
    const uint32_t sB = sA + A_BYTES;             // B: fp16 U[b] half [128][264]

    const int tid  = threadIdx.x;
    const int lane = tid & 31;
    const int wid  = tid >> 5;
    const int b    = blockIdx.z;
    const int nh   = blockIdx.y;                  // N-half: 0 or 1
    const int m0   = blockIdx.x * M_TILE;
    const float* __restrict__ Ub = U + (size_t)b * K_DIM * N_DIM + nh * N_HALF;

    // ---- prologue: fill resident B half (fp32 -> fp16), 32 float4 per thread ----
#pragma unroll 8
    for (int it = 0; it < 32; ++it) {
        const int idx = it * THREADS + tid;
        const int k   = idx >> 6;            // 0..127
        const int n4  = idx & 63;            // float4 index within half row (256/4)
        const float4 v = *reinterpret_cast<const float4*>(Ub + (size_t)k * N_DIM + n4 * 4);
        uint2 p;
        p.x = pack_f16x2(v.x, v.y);
        p.y = pack_f16x2(v.z, v.w);
        *reinterpret_cast<uint2*>(smem + A_BYTES + (size_t)k * B_PITCH_B + n4 * 8) = p;
    }

    // ---- fused softmax: 2 threads per row, each owns 64 of 128 cols -> fp16 A ----
    {
        const int row  = tid >> 1;
        const int half = tid & 1;
        const float4* sp = reinterpret_cast<const float4*>(
            S + (size_t)(b * T_SEQ + m0 + row) * K_DIM + half * 64);
        float4 e[16];
        float sum = 0.f;
#pragma unroll
        for (int i = 0; i < 16; ++i) {
            float4 x = sp[i];
            e[i].x = __expf(x.x); e[i].y = __expf(x.y);
            e[i].z = __expf(x.z); e[i].w = __expf(x.w);
            sum += (e[i].x + e[i].y) + (e[i].z + e[i].w);
        }
        sum += __shfl_xor_sync(0xffffffffu, sum, 1);
        const float inv = 1.0f / sum;
        char* arow = smem + (size_t)row * A_PITCH_B + half * 128;
#pragma unroll
        for (int i = 0; i < 8; ++i) {
            uint4 t;
            t.x = pack_f16x2(e[2 * i].x * inv,     e[2 * i].y * inv);
            t.y = pack_f16x2(e[2 * i].z * inv,     e[2 * i].w * inv);
            t.z = pack_f16x2(e[2 * i + 1].x * inv, e[2 * i + 1].y * inv);
            t.w = pack_f16x2(e[2 * i + 1].z * inv, e[2 * i + 1].w * inv);
            *reinterpret_cast<uint4*>(arow + i * 16) = t;
        }
    }

    __syncthreads();   // the only CTA barrier

    // ---- fragment base addresses ----
    const int warpM = wid & 1;
    const int warpN = wid >> 1;
    const int l8 = lane & 7;
    const int tl = lane >> 3;
    // A ldmatrix.x4 (row-major m16 x k16 tile): tiles {m-half, k-half}
    uint32_t aAddr[4];
#pragma unroll
    for (int mf = 0; mf < 4; ++mf) {
        const int row = warpM * 64 + mf * 16 + ((tl & 1) << 3) + l8;
        aAddr[mf] = sA + (uint32_t)row * A_PITCH_B + (uint32_t)(tl >> 1) * 16u;
    }
    // B ldmatrix.x4.trans (K-major): lanes 0-15 -> k=lane&15 at n-offset 0,
    // lanes 16-31 -> same k at n-offset +8 cols.
    const uint32_t bLaneOff =
        (uint32_t)(lane & 15) * B_PITCH_B + (uint32_t)((lane >> 4) << 3) * 2u;
    const uint32_t bWarpCol = (uint32_t)(warpN * 32) * 2u;

    float* outBase = Out + (size_t)(b * T_SEQ + m0) * N_DIM + nh * N_HALF;

    // ---- main loop: 2 N-chunks, no barriers, resident B ----
#pragma unroll 1
    for (int c = 0; c < NCHUNKS; ++c) {
        const uint32_t bChunk = sB + bLaneOff + bWarpCol + (uint32_t)(c * NCHUNK) * 2u;

        float acc[4][4][4];
#pragma unroll
        for (int mf = 0; mf < 4; ++mf)
#pragma unroll
            for (int nf = 0; nf < 4; ++nf)
#pragma unroll
                for (int r = 0; r < 4; ++r) acc[mf][nf][r] = 0.f;

        uint32_t a[2][4][4];
        uint32_t bf[2][2][4];

        // prefetch kstep 0
#pragma unroll
        for (int mf = 0; mf < 4; ++mf)
            ldsm_x4(a[0][mf][0], a[0][mf][1], a[0][mf][2], a[0][mf][3], aAddr[mf]);
#pragma unroll
        for (int np = 0; np < 2; ++np)
            ldsm_x4_trans(bf[0][np][0], bf[0][np][1], bf[0][np][2], bf[0][np][3],
                          bChunk + (uint32_t)(np * 16) * 2u);

#pragma unroll
        for (int s = 0; s < 8; ++s) {
            const int cur = s & 1;
            const int nxt = cur ^ 1;
            if (s < 7) {
#pragma unroll
                for (int mf = 0; mf < 4; ++mf)
                    ldsm_x4(a[nxt][mf][0], a[nxt][mf][1], a[nxt][mf][2], a[nxt][mf][3],
                            aAddr[mf] + (uint32_t)(s + 1) * 32u);
#pragma unroll
                for (int np = 0; np < 2; ++np)
                    ldsm_x4_trans(bf[nxt][np][0], bf[nxt][np][1],
                                  bf[nxt][np][2], bf[nxt][np][3],
                                  bChunk + (uint32_t)(np * 16) * 2u
                                         + (uint32_t)(s + 1) * (16u * B_PITCH_B));
            }
#pragma unroll
            for (int mf = 0; mf < 4; ++mf)
#pragma unroll
                for (int nf = 0; nf < 4; ++nf)
                    mma_f16(acc[mf][nf][0], acc[mf][nf][1],
                            acc[mf][nf][2], acc[mf][nf][3],
                            a[cur][mf][0], a[cur][mf][1], a[cur][mf][2], a[cur][mf][3],
                            bf[cur][nf >> 1][2 * (nf & 1)], bf[cur][nf >> 1][2 * (nf & 1) + 1]);
        }

        // ---- epilogue: stream accumulators to GMEM ----
        const int colBase = c * NCHUNK + warpN * 32 + 2 * (lane & 3);
        const int rowBase = warpM * 64 + (lane >> 2);
#pragma unroll
        for (int mf = 0; mf < 4; ++mf) {
            const int r0 = rowBase + mf * 16;
#pragma unroll
            for (int nf = 0; nf < 4; ++nf) {
                const int col = colBase + nf * 8;
                float2 v0 = make_float2(acc[mf][nf][0], acc[mf][nf][1]);
                float2 v1 = make_float2(acc[mf][nf][2], acc[mf][nf][3]);
                __stcs(reinterpret_cast<float2*>(outBase + (size_t)r0 * N_DIM + col), v0);
                __stcs(reinterpret_cast<float2*>(outBase + (size_t)(r0 + 8) * N_DIM + col), v1);
            }
        }
    }
}

extern "C" void kernel_launch(void* const* d_in, const int* in_sizes, int n_in,
                              void* d_out, int out_size)
{
    const float* U = (const float*)d_in[0];
    const float* S = (const float*)d_in[1];
    // Robustness: U has 8.4M elements, S has 33.5M. Swap if order differs.
    if (n_in >= 2 && in_sizes[0] == B_BATCH * T_SEQ * K_DIM) {
        const float* t = U; U = S; S = t;
    }
    float* Out = (float*)d_out;

    static int attr_set = 0;
    if (!attr_set) {
        cudaFuncSetAttribute(C2Q_15032385536516_kernel,
                             cudaFuncAttributeMaxDynamicSharedMemorySize, SMEM_TOTAL);
        attr_set = 1;
    }
    dim3 grid(T_SEQ / M_TILE, 2, B_BATCH);  // (16, 2, 128)
    C2Q_15032385536516_kernel<<<grid, THREADS, SMEM_TOTAL>>>(U, S, Out);
}

// round 7
// speedup vs baseline: 1.0643x; 1.0643x over previous
#include <cuda_runtime.h>
#include <cuda_fp16.h>
#include <cstdint>

// Problem dims
#define B_BATCH   128
#define T_SEQ     2048
#define K_DIM     128    // J (softmax / contraction dim)
#define N_DIM     512    // d (output feature dim)
#define M_TILE    128
#define NCHUNK    128    // N streamed in 4 chunks of 128 cols
#define NCHUNKS   4
#define THREADS   256

#define A_PITCH_B 272    // bytes per A row (136 fp16; +8 pad -> conflict-free ldsm)
#define B_PITCH_B 272    // bytes per B chunk row (136 fp16)
#define A_BYTES   (128 * A_PITCH_B)     // 34,816
#define B_BYTES   (128 * B_PITCH_B)     // 34,816 per buffer
static constexpr unsigned SMEM_TOTAL = A_BYTES + 2 * B_BYTES;  // 104,448 -> 2 CTAs/SM

// ---------------- helpers ----------------
static __device__ __forceinline__ uint32_t smem_u32(const void* p) {
    uint32_t a;
    asm("{ .reg .u64 t; cvta.to.shared.u64 t, %1; cvt.u32.u64 %0, t; }" : "=r"(a) : "l"(p));
    return a;
}

// pack two f32 -> f16x2 (lo = x, hi = y)
static __device__ __forceinline__ uint32_t pack_f16x2(float x, float y) {
    uint32_t r;
    asm("cvt.rn.f16x2.f32 %0, %1, %2;" : "=r"(r) : "f"(y), "f"(x));
    return r;
}

static __device__ __forceinline__ void ldsm_x4(
    uint32_t& r0, uint32_t& r1, uint32_t& r2, uint32_t& r3, uint32_t addr)
{
    asm volatile("ldmatrix.sync.aligned.m8n8.x4.shared.b16 {%0,%1,%2,%3}, [%4];"
                 : "=r"(r0), "=r"(r1), "=r"(r2), "=r"(r3) : "r"(addr));
}

static __device__ __forceinline__ void ldsm_x4_trans(
    uint32_t& r0, uint32_t& r1, uint32_t& r2, uint32_t& r3, uint32_t addr)
{
    asm volatile("ldmatrix.sync.aligned.m8n8.x4.trans.shared.b16 {%0,%1,%2,%3}, [%4];"
                 : "=r"(r0), "=r"(r1), "=r"(r2), "=r"(r3) : "r"(addr));
}

static __device__ __forceinline__ void mma_f16(
    float& c0, float& c1, float& c2, float& c3,
    uint32_t a0, uint32_t a1, uint32_t a2, uint32_t a3,
    uint32_t b0, uint32_t b1)
{
    asm volatile(
        "mma.sync.aligned.m16n8k16.row.col.f32.f16.f16.f32 "
        "{%0,%1,%2,%3}, {%4,%5,%6,%7}, {%8,%9}, {%0,%1,%2,%3};"
        : "+f"(c0), "+f"(c1), "+f"(c2), "+f"(c3)
        : "r"(a0), "r"(a1), "r"(a2), "r"(a3), "r"(b0), "r"(b1));
}

// fill one 128x128 B chunk: LDG fp32 -> cvt fp16 -> STS (16 float4 per thread)
static __device__ __forceinline__ void fill_b_chunk(
    char* __restrict__ dst, const float* __restrict__ src, int tid)
{
#pragma unroll
    for (int it = 0; it < 16; ++it) {
        const int idx = it * THREADS + tid;
        const int k   = idx >> 5;            // 0..127
        const int n4  = idx & 31;            // float4 index within chunk row
        const float4 v = *reinterpret_cast<const float4*>(src + (size_t)k * N_DIM + n4 * 4);
        uint2 p;
        p.x = pack_f16x2(v.x, v.y);
        p.y = pack_f16x2(v.z, v.w);
        *reinterpret_cast<uint2*>(dst + (size_t)k * B_PITCH_B + n4 * 8) = p;
    }
}

// ---------------- kernel ----------------
// Grid: (16 M-tiles, 128 batches). 256 threads = 8 warps. 2 CTAs/SM.
// Full N per CTA; B streamed in 4 fp16 double-buffered chunks.
// Warp layout per chunk: warpM = wid&1 (2 x 64 rows), warpN = wid>>1 (4 x 32 cols).
__global__ void __launch_bounds__(THREADS, 2)
C2Q_15032385536516_kernel(const float* __restrict__ U,
                          const float* __restrict__ S,
                          float* __restrict__ Out)
{
    extern __shared__ char smem[];
    const uint32_t sA = smem_u32(smem);           // A: fp16 probs [128][136]
    const uint32_t sB = sA + A_BYTES;             // B: 2 x fp16 chunk [128][136]

    const int tid  = threadIdx.x;
    const int lane = tid & 31;
    const int wid  = tid >> 5;
    const int b    = blockIdx.y;
    const int m0   = blockIdx.x * M_TILE;
    const float* __restrict__ Ub = U + (size_t)b * K_DIM * N_DIM;

    // ---- prologue: fill B chunk 0 into buffer 0 ----
    fill_b_chunk(smem + A_BYTES, Ub, tid);

    // ---- fused softmax: 2 threads per row, each owns 64 of 128 cols -> fp16 A ----
    {
        const int row  = tid >> 1;
        const int half = tid & 1;
        const float4* sp = reinterpret_cast<const float4*>(
            S + (size_t)(b * T_SEQ + m0 + row) * K_DIM + half * 64);
        float4 e[16];
        float sum = 0.f;
#pragma unroll
        for (int i = 0; i < 16; ++i) {
            float4 x = sp[i];
            e[i].x = __expf(x.x); e[i].y = __expf(x.y);
            e[i].z = __expf(x.z); e[i].w = __expf(x.w);
            sum += (e[i].x + e[i].y) + (e[i].z + e[i].w);
        }
        sum += __shfl_xor_sync(0xffffffffu, sum, 1);
        const float inv = 1.0f / sum;
        char* arow = smem + (size_t)row * A_PITCH_B + half * 128;
#pragma unroll
        for (int i = 0; i < 8; ++i) {
            uint4 t;
            t.x = pack_f16x2(e[2 * i].x * inv,     e[2 * i].y * inv);
            t.y = pack_f16x2(e[2 * i].z * inv,     e[2 * i].w * inv);
            t.z = pack_f16x2(e[2 * i + 1].x * inv, e[2 * i + 1].y * inv);
            t.w = pack_f16x2(e[2 * i + 1].z * inv, e[2 * i + 1].w * inv);
            *reinterpret_cast<uint4*>(arow + i * 16) = t;
        }
    }

    __syncthreads();

    // ---- fragment base addresses ----
    const int warpM = wid & 1;
    const int warpN = wid >> 1;
    const int l8 = lane & 7;
    const int tl = lane >> 3;
    // A ldmatrix.x4 (row-major m16 x k16 tile): tiles {m-half, k-half}
    uint32_t aAddr[4];
#pragma unroll
    for (int mf = 0; mf < 4; ++mf) {
        const int row = warpM * 64 + mf * 16 + ((tl & 1) << 3) + l8;
        aAddr[mf] = sA + (uint32_t)row * A_PITCH_B + (uint32_t)(tl >> 1) * 16u;
    }
    // B ldmatrix.x4.trans (K-major): lanes 0-15 -> k=lane&15 at n-offset 0,
    // lanes 16-31 -> same k at n-offset +8 cols.
    const uint32_t bLaneOff =
        (uint32_t)(lane & 15) * B_PITCH_B + (uint32_t)((lane >> 4) << 3) * 2u;
    const uint32_t bWarpCol = (uint32_t)(warpN * 32) * 2u;

    float* outBase = Out + (size_t)(b * T_SEQ + m0) * N_DIM;

    // ---- main loop: 4 streamed chunks, double-buffered B ----
#pragma unroll 1
    for (int c = 0; c < NCHUNKS; ++c) {
        const uint32_t bBuf = sB + (uint32_t)(c & 1) * B_BYTES + bLaneOff + bWarpCol;

        float acc[4][4][4];
#pragma unroll
        for (int mf = 0; mf < 4; ++mf)
#pragma unroll
            for (int nf = 0; nf < 4; ++nf)
#pragma unroll
                for (int r = 0; r < 4; ++r) acc[mf][nf][r] = 0.f;

#pragma unroll
        for (int s = 0; s < 8; ++s) {
            uint32_t a[4][4];
#pragma unroll
            for (int mf = 0; mf < 4; ++mf)
                ldsm_x4(a[mf][0], a[mf][1], a[mf][2], a[mf][3],
                        aAddr[mf] + (uint32_t)s * 32u);
            uint32_t bf[2][4];
#pragma unroll
            for (int np = 0; np < 2; ++np)
                ldsm_x4_trans(bf[np][0], bf[np][1], bf[np][2], bf[np][3],
                              bBuf + (uint32_t)(np * 16) * 2u
                                   + (uint32_t)s * (16u * B_PITCH_B));
#pragma unroll
            for (int mf = 0; mf < 4; ++mf)
#pragma unroll
                for (int nf = 0; nf < 4; ++nf)
                    mma_f16(acc[mf][nf][0], acc[mf][nf][1],
                            acc[mf][nf][2], acc[mf][nf][3],
                            a[mf][0], a[mf][1], a[mf][2], a[mf][3],
                            bf[nf >> 1][2 * (nf & 1)], bf[nf >> 1][2 * (nf & 1) + 1]);
        }

        // ---- fill next chunk into the other buffer (readers of it synced last iter) ----
        if (c + 1 < NCHUNKS)
            fill_b_chunk(smem + A_BYTES + (size_t)((c + 1) & 1) * B_BYTES,
                         Ub + (c + 1) * NCHUNK, tid);

        // ---- epilogue: stream accumulators to GMEM ----
        const int colBase = c * NCHUNK + warpN * 32 + 2 * (lane & 3);
        const int rowBase = warpM * 64 + (lane >> 2);
#pragma unroll
        for (int mf = 0; mf < 4; ++mf) {
            const int r0 = rowBase + mf * 16;
#pragma unroll
            for (int nf = 0; nf < 4; ++nf) {
                const int col = colBase + nf * 8;
                float2 v0 = make_float2(acc[mf][nf][0], acc[mf][nf][1]);
                float2 v1 = make_float2(acc[mf][nf][2], acc[mf][nf][3]);
                __stcs(reinterpret_cast<float2*>(outBase + (size_t)r0 * N_DIM + col), v0);
                __stcs(reinterpret_cast<float2*>(outBase + (size_t)(r0 + 8) * N_DIM + col), v1);
            }
        }

        __syncthreads();   // buffer handoff
    }
}

extern "C" void kernel_launch(void* const* d_in, const int* in_sizes, int n_in,
                              void* d_out, int out_size)
{
    const float* U = (const float*)d_in[0];
    const float* S = (const float*)d_in[1];
    // Robustness: U has 8.4M elements, S has 33.5M. Swap if order differs.
    if (n_in >= 2 && in_sizes[0] == B_BATCH * T_SEQ * K_DIM) {
        const float* t = U; U = S; S = t;
    }
    float* Out = (float*)d_out;

    static int attr_set = 0;
    if (!attr_set) {
        cudaFuncSetAttribute(C2Q_15032385536516_kernel,
                             cudaFuncAttributeMaxDynamicSharedMemorySize, SMEM_TOTAL);
        attr_set = 1;
    }
    dim3 grid(T_SEQ / M_TILE, B_BATCH, 1);  // (16, 128)
    C2Q_15032385536516_kernel<<<grid, THREADS, SMEM_TOTAL>>>(U, S, Out);
}

// round 8
// speedup vs baseline: 1.2078x; 1.1349x over previous
#include <cuda_runtime.h>
#include <cuda_fp16.h>
#include <cstdint>

// Problem dims
#define B_BATCH   128
#define T_SEQ     2048
#define K_DIM     128    // J (softmax / contraction dim)
#define N_DIM     512    // d (output feature dim)
#define M_TILE    128
#define NCHUNK    128    // N streamed in 4 chunks of 128 cols
#define NCHUNKS   4
#define THREADS   256

#define A_PITCH_B 272    // bytes per A row (136 fp16; 8-half pad -> conflict-free ldsm)
#define B_PITCH_B 272    // bytes per B chunk row (128 data halfs + 8 pad)
#define A_BYTES   (128 * A_PITCH_B)     // 34,816
#define B_BYTES   (128 * B_PITCH_B)     // 34,816 per buffer
static constexpr unsigned SMEM_TOTAL = A_BYTES + 2 * B_BYTES;  // 104,448 -> 2 CTAs/SM

// fp16 copy of U, produced once per launch by convert_U_kernel.
// 128*128*512 halfs = 16,777,216 B stored as uint2 (8B) -> 2,097,152 entries.
__device__ __align__(16) uint2 g_U16[(size_t)B_BATCH * K_DIM * N_DIM / 4];

// ---------------- helpers ----------------
static __device__ __forceinline__ uint32_t smem_u32(const void* p) {
    uint32_t a;
    asm("{ .reg .u64 t; cvta.to.shared.u64 t, %1; cvt.u32.u64 %0, t; }" : "=r"(a) : "l"(p));
    return a;
}

// pack two f32 -> f16x2 (lo = x, hi = y)
static __device__ __forceinline__ uint32_t pack_f16x2(float x, float y) {
    uint32_t r;
    asm("cvt.rn.f16x2.f32 %0, %1, %2;" : "=r"(r) : "f"(y), "f"(x));
    return r;
}

static __device__ __forceinline__ void cp_async16(uint32_t saddr, const void* gptr) {
    asm volatile("cp.async.cg.shared.global [%0], [%1], 16;"
                 :: "r"(saddr), "l"(gptr) : "memory");
}
static __device__ __forceinline__ void cp_commit() {
    asm volatile("cp.async.commit_group;" ::: "memory");
}
template <int N>
static __device__ __forceinline__ void cp_wait() {
    asm volatile("cp.async.wait_group %0;" :: "n"(N) : "memory");
}

static __device__ __forceinline__ void ldsm_x4(
    uint32_t& r0, uint32_t& r1, uint32_t& r2, uint32_t& r3, uint32_t addr)
{
    asm volatile("ldmatrix.sync.aligned.m8n8.x4.shared.b16 {%0,%1,%2,%3}, [%4];"
                 : "=r"(r0), "=r"(r1), "=r"(r2), "=r"(r3) : "r"(addr));
}

static __device__ __forceinline__ void ldsm_x4_trans(
    uint32_t& r0, uint32_t& r1, uint32_t& r2, uint32_t& r3, uint32_t addr)
{
    asm volatile("ldmatrix.sync.aligned.m8n8.x4.trans.shared.b16 {%0,%1,%2,%3}, [%4];"
                 : "=r"(r0), "=r"(r1), "=r"(r2), "=r"(r3) : "r"(addr));
}

static __device__ __forceinline__ void mma_f16(
    float& c0, float& c1, float& c2, float& c3,
    uint32_t a0, uint32_t a1, uint32_t a2, uint32_t a3,
    uint32_t b0, uint32_t b1)
{
    asm volatile(
        "mma.sync.aligned.m16n8k16.row.col.f32.f16.f16.f32 "
        "{%0,%1,%2,%3}, {%4,%5,%6,%7}, {%8,%9}, {%0,%1,%2,%3};"
        : "+f"(c0), "+f"(c1), "+f"(c2), "+f"(c3)
        : "r"(a0), "r"(a1), "r"(a2), "r"(a3), "r"(b0), "r"(b1));
}

// ---------------- pre-kernel: U fp32 -> fp16 scratch ----------------
__global__ void __launch_bounds__(256)
convert_U_kernel(const float* __restrict__ U)
{
    const int idx = blockIdx.x * 256 + threadIdx.x;     // one float4 per thread
    const float4 v = reinterpret_cast<const float4*>(U)[idx];
    uint2 p;
    p.x = pack_f16x2(v.x, v.y);
    p.y = pack_f16x2(v.z, v.w);
    g_U16[idx] = p;
}

// issue one 128x128 fp16 B chunk via cp.async (8 x 16B per thread)
static __device__ __forceinline__ void issue_b_chunk(
    uint32_t dst, const char* __restrict__ src16, int tid)
{
#pragma unroll
    for (int it = 0; it < 8; ++it) {
        const int idx = it * THREADS + tid;
        const int k   = idx >> 4;            // 0..127
        const int g   = idx & 15;            // 16B group within chunk row
        cp_async16(dst + (uint32_t)k * B_PITCH_B + (uint32_t)g * 16u,
                   src16 + (size_t)k * (N_DIM * 2) + g * 16);
    }
    cp_commit();
}

// ---------------- main kernel ----------------
// Grid: (16 M-tiles, 128 batches). 256 threads = 8 warps. 2 CTAs/SM.
// Full N per CTA; B streamed from fp16 scratch in 4 double-buffered chunks.
// Warp layout per chunk: warpM = wid&1 (2 x 64 rows), warpN = wid>>1 (4 x 32 cols).
__global__ void __launch_bounds__(THREADS, 2)
C2Q_15032385536516_kernel(const float* __restrict__ S,
                          float* __restrict__ Out)
{
    extern __shared__ char smem[];
    const uint32_t sA = smem_u32(smem);           // A: fp16 probs [128][136]
    const uint32_t sB = sA + A_BYTES;             // B: 2 x fp16 chunk [128][136]

    const int tid  = threadIdx.x;
    const int lane = tid & 31;
    const int wid  = tid >> 5;
    const int b    = blockIdx.y;
    const int m0   = blockIdx.x * M_TILE;
    const char* __restrict__ Ub16 =
        reinterpret_cast<const char*>(g_U16) + (size_t)b * K_DIM * N_DIM * 2;

    // ---- prologue: issue B chunk 0 (arrives during softmax) ----
    issue_b_chunk(sB, Ub16, tid);

    // ---- fused softmax: 2 threads per row, each owns 64 of 128 cols -> fp16 A ----
    {
        const int row  = tid >> 1;
        const int half = tid & 1;
        const float4* sp = reinterpret_cast<const float4*>(
            S + (size_t)(b * T_SEQ + m0 + row) * K_DIM + half * 64);
        float4 e[16];
        float sum = 0.f;
#pragma unroll
        for (int i = 0; i < 16; ++i) {
            float4 x = sp[i];
            e[i].x = __expf(x.x); e[i].y = __expf(x.y);
            e[i].z = __expf(x.z); e[i].w = __expf(x.w);
            sum += (e[i].x + e[i].y) + (e[i].z + e[i].w);
        }
        sum += __shfl_xor_sync(0xffffffffu, sum, 1);
        const float inv = 1.0f / sum;
        char* arow = smem + (size_t)row * A_PITCH_B + half * 128;
#pragma unroll
        for (int i = 0; i < 8; ++i) {
            uint4 t;
            t.x = pack_f16x2(e[2 * i].x * inv,     e[2 * i].y * inv);
            t.y = pack_f16x2(e[2 * i].z * inv,     e[2 * i].w * inv);
            t.z = pack_f16x2(e[2 * i + 1].x * inv, e[2 * i + 1].y * inv);
            t.w = pack_f16x2(e[2 * i + 1].z * inv, e[2 * i + 1].w * inv);
            *reinterpret_cast<uint4*>(arow + i * 16) = t;
        }
    }

    cp_wait<0>();
    __syncthreads();   // A visible + chunk 0 landed

    // ---- fragment base addresses ----
    const int warpM = wid & 1;
    const int warpN = wid >> 1;
    const int l8 = lane & 7;
    const int tl = lane >> 3;
    // A ldmatrix.x4 (row-major m16 x k16 tile): tiles {m-half, k-half}
    uint32_t aAddr[4];
#pragma unroll
    for (int mf = 0; mf < 4; ++mf) {
        const int row = warpM * 64 + mf * 16 + ((tl & 1) << 3) + l8;
        aAddr[mf] = sA + (uint32_t)row * A_PITCH_B + (uint32_t)(tl >> 1) * 16u;
    }
    // B ldmatrix.x4.trans (K-major): lanes 0-15 -> k=lane&15 at n-offset 0,
    // lanes 16-31 -> same k at n-offset +8 cols.
    const uint32_t bLaneOff =
        (uint32_t)(lane & 15) * B_PITCH_B + (uint32_t)((lane >> 4) << 3) * 2u;
    const uint32_t bWarpCol = (uint32_t)(warpN * 32) * 2u;

    float* outBase = Out + (size_t)(b * T_SEQ + m0) * N_DIM;

    // ---- main loop: 4 streamed chunks, double-buffered B via cp.async ----
#pragma unroll 1
    for (int c = 0; c < NCHUNKS; ++c) {
        // issue next chunk first: its DRAM latency hides behind MMA + epilogue.
        // Buffer (c+1)&1 was last read in MMA(c-1); barrier at end of iter c-1
        // guarantees all warps are done with it.
        if (c + 1 < NCHUNKS)
            issue_b_chunk(sB + (uint32_t)((c + 1) & 1) * B_BYTES,
                          Ub16 + (size_t)(c + 1) * NCHUNK * 2, tid);

        const uint32_t bBuf = sB + (uint32_t)(c & 1) * B_BYTES + bLaneOff + bWarpCol;

        float acc[4][4][4];
#pragma unroll
        for (int mf = 0; mf < 4; ++mf)
#pragma unroll
            for (int nf = 0; nf < 4; ++nf)
#pragma unroll
                for (int r = 0; r < 4; ++r) acc[mf][nf][r] = 0.f;

#pragma unroll
        for (int s = 0; s < 8; ++s) {
            uint32_t a[4][4];
#pragma unroll
            for (int mf = 0; mf < 4; ++mf)
                ldsm_x4(a[mf][0], a[mf][1], a[mf][2], a[mf][3],
                        aAddr[mf] + (uint32_t)s * 32u);
            uint32_t bf[2][4];
#pragma unroll
            for (int np = 0; np < 2; ++np)
                ldsm_x4_trans(bf[np][0], bf[np][1], bf[np][2], bf[np][3],
                              bBuf + (uint32_t)(np * 16) * 2u
                                   + (uint32_t)s * (16u * B_PITCH_B));
#pragma unroll
            for (int mf = 0; mf < 4; ++mf)
#pragma unroll
                for (int nf = 0; nf < 4; ++nf)
                    mma_f16(acc[mf][nf][0], acc[mf][nf][1],
                            acc[mf][nf][2], acc[mf][nf][3],
                            a[mf][0], a[mf][1], a[mf][2], a[mf][3],
                            bf[nf >> 1][2 * (nf & 1)], bf[nf >> 1][2 * (nf & 1) + 1]);
        }

        // ---- epilogue: stream accumulators to GMEM ----
        const int colBase = c * NCHUNK + warpN * 32 + 2 * (lane & 3);
        const int rowBase = warpM * 64 + (lane >> 2);
#pragma unroll
        for (int mf = 0; mf < 4; ++mf) {
            const int r0 = rowBase + mf * 16;
#pragma unroll
            for (int nf = 0; nf < 4; ++nf) {
                const int col = colBase + nf * 8;
                float2 v0 = make_float2(acc[mf][nf][0], acc[mf][nf][1]);
                float2 v1 = make_float2(acc[mf][nf][2], acc[mf][nf][3]);
                __stcs(reinterpret_cast<float2*>(outBase + (size_t)r0 * N_DIM + col), v0);
                __stcs(reinterpret_cast<float2*>(outBase + (size_t)(r0 + 8) * N_DIM + col), v1);
            }
        }

        if (c + 1 < NCHUNKS) {
            cp_wait<0>();
            __syncthreads();   // next buffer landed + all warps done with old one
        }
    }
}

extern "C" void kernel_launch(void* const* d_in, const int* in_sizes, int n_in,
                              void* d_out, int out_size)
{
    const float* U = (const float*)d_in[0];
    const float* S = (const float*)d_in[1];
    // Robustness: U has 8.4M elements, S has 33.5M. Swap if order differs.
    if (n_in >= 2 && in_sizes[0] == B_BATCH * T_SEQ * K_DIM) {
        const float* t = U; U = S; S = t;
    }
    float* Out = (float*)d_out;

    static int attr_set = 0;
    if (!attr_set) {
        cudaFuncSetAttribute(C2Q_15032385536516_kernel,
                             cudaFuncAttributeMaxDynamicSharedMemorySize, SMEM_TOTAL);
        attr_set = 1;
    }

    // 1) convert U fp32 -> fp16 scratch (one float4 per thread)
    const int n_f4 = B_BATCH * K_DIM * N_DIM / 4;      // 2,097,152
    convert_U_kernel<<<n_f4 / 256, 256>>>(U);

    // 2) main fused softmax-GEMM
    dim3 grid(T_SEQ / M_TILE, B_BATCH, 1);  // (16, 128)
    C2Q_15032385536516_kernel<<<grid, THREADS, SMEM_TOTAL>>>(S, Out);
}

// round 9
// speedup vs baseline: 1.2743x; 1.0550x over previous
#include <cuda_runtime.h>
#include <cuda_fp16.h>
#include <cstdint>

// Problem dims
#define B_BATCH   128
#define T_SEQ     2048
#define K_DIM     128    // J (softmax / contraction dim)
#define N_DIM     512    // d (output feature dim)
#define M_TILE    128
#define NCHUNK    128    // N processed in 4 register chunks of 128
#define NCHUNKS   4
#define THREADS   256

#define TILES_PER_B   16          // T_SEQ / M_TILE
#define UNIT_TILES    2           // tiles per work unit
#define NUNITS        1024        // 2048 tiles / 2
#define GRID_MAIN     152         // persistent CTAs (1/SM on GB300)

#define A_PITCH_B 272    // bytes per A row (136 fp16; 8-half pad -> conflict-free ldsm)
#define B_PITCH_B 1040   // bytes per B row (520 fp16; 8-half pad -> conflict-free ldsm.trans)
#define A_BYTES   (128 * A_PITCH_B)     // 34,816
#define B_BYTES   (128 * B_PITCH_B)     // 133,120
static constexpr unsigned SMEM_TOTAL = A_BYTES + B_BYTES + 16;  // + mailbox

// fp16 copy of U (one-time convert): 16.7 MB as uint2.
__device__ __align__(16) uint2 g_U16[(size_t)B_BATCH * K_DIM * N_DIM / 4];
__device__ unsigned g_counter;

// ---------------- helpers ----------------
static __device__ __forceinline__ uint32_t smem_u32(const void* p) {
    uint32_t a;
    asm("{ .reg .u64 t; cvta.to.shared.u64 t, %1; cvt.u32.u64 %0, t; }" : "=r"(a) : "l"(p));
    return a;
}

static __device__ __forceinline__ uint32_t pack_f16x2(float x, float y) {
    uint32_t r;
    asm("cvt.rn.f16x2.f32 %0, %1, %2;" : "=r"(r) : "f"(y), "f"(x));
    return r;
}

static __device__ __forceinline__ void cp_async16(uint32_t saddr, const void* gptr) {
    asm volatile("cp.async.cg.shared.global [%0], [%1], 16;"
                 :: "r"(saddr), "l"(gptr) : "memory");
}
static __device__ __forceinline__ void cp_commit() {
    asm volatile("cp.async.commit_group;" ::: "memory");
}
template <int N>
static __device__ __forceinline__ void cp_wait() {
    asm volatile("cp.async.wait_group %0;" :: "n"(N) : "memory");
}

static __device__ __forceinline__ void ldsm_x4(
    uint32_t& r0, uint32_t& r1, uint32_t& r2, uint32_t& r3, uint32_t addr)
{
    asm volatile("ldmatrix.sync.aligned.m8n8.x4.shared.b16 {%0,%1,%2,%3}, [%4];"
                 : "=r"(r0), "=r"(r1), "=r"(r2), "=r"(r3) : "r"(addr));
}

static __device__ __forceinline__ void ldsm_x4_trans(
    uint32_t& r0, uint32_t& r1, uint32_t& r2, uint32_t& r3, uint32_t addr)
{
    asm volatile("ldmatrix.sync.aligned.m8n8.x4.trans.shared.b16 {%0,%1,%2,%3}, [%4];"
                 : "=r"(r0), "=r"(r1), "=r"(r2), "=r"(r3) : "r"(addr));
}

static __device__ __forceinline__ void mma_f16(
    float& c0, float& c1, float& c2, float& c3,
    uint32_t a0, uint32_t a1, uint32_t a2, uint32_t a3,
    uint32_t b0, uint32_t b1)
{
    asm volatile(
        "mma.sync.aligned.m16n8k16.row.col.f32.f16.f16.f32 "
        "{%0,%1,%2,%3}, {%4,%5,%6,%7}, {%8,%9}, {%0,%1,%2,%3};"
        : "+f"(c0), "+f"(c1), "+f"(c2), "+f"(c3)
        : "r"(a0), "r"(a1), "r"(a2), "r"(a3), "r"(b0), "r"(b1));
}

// ---------------- pre-kernel: U fp32 -> fp16 scratch + counter reset ----------------
__global__ void __launch_bounds__(256)
convert_U_kernel(const float* __restrict__ U)
{
    if (blockIdx.x == 0 && threadIdx.x == 0) g_counter = 0;
    const int idx = blockIdx.x * 256 + threadIdx.x;     // one float4 per thread
    const float4 v = reinterpret_cast<const float4*>(U)[idx];
    uint2 p;
    p.x = pack_f16x2(v.x, v.y);
    p.y = pack_f16x2(v.z, v.w);
    g_U16[idx] = p;
}

// issue full 128x512 fp16 B tile via cp.async (32 x 16B per thread)
static __device__ __forceinline__ void issue_b_full(uint32_t sB, int b, int tid)
{
    const char* src = reinterpret_cast<const char*>(g_U16) + (size_t)b * K_DIM * N_DIM * 2;
#pragma unroll
    for (int it = 0; it < 32; ++it) {
        const int idx = it * THREADS + tid;
        const int k   = idx >> 6;            // 0..127
        const int g   = idx & 63;            // 16B group within 1024B row
        cp_async16(sB + (uint32_t)k * B_PITCH_B + (uint32_t)g * 16u,
                   src + (size_t)k * 1024 + g * 16);
    }
    cp_commit();
}

// ---------------- main kernel ----------------
// 152 persistent CTAs, 256 threads (8 warps), 1 CTA/SM.
// Work unit = 2 M-tiles of one batch (atomic counter). U16[b] resident in smem.
// Warp layout: warpM = wid&1 (2 x 64 rows), warpN = wid>>1 (4 x 32 cols per chunk).
__global__ void __launch_bounds__(THREADS, 1)
C2Q_15032385536516_kernel(const float* __restrict__ S,
                          float* __restrict__ Out)
{
    extern __shared__ char smem[];
    const uint32_t sA = smem_u32(smem);
    const uint32_t sB = sA + A_BYTES;
    volatile int* mail = reinterpret_cast<volatile int*>(smem + A_BYTES + B_BYTES);

    const int tid  = threadIdx.x;
    const int lane = tid & 31;
    const int wid  = tid >> 5;

    // ---- fragment base addresses (fixed for all tiles) ----
    const int warpM = wid & 1;
    const int warpN = wid >> 1;
    const int l8 = lane & 7;
    const int tl = lane >> 3;
    uint32_t aAddr[4];
#pragma unroll
    for (int mf = 0; mf < 4; ++mf) {
        const int row = warpM * 64 + mf * 16 + ((tl & 1) << 3) + l8;
        aAddr[mf] = sA + (uint32_t)row * A_PITCH_B + (uint32_t)(tl >> 1) * 16u;
    }
    const uint32_t bLaneOff =
        (uint32_t)(lane & 15) * B_PITCH_B + (uint32_t)((lane >> 4) << 3) * 2u;
    const uint32_t bWarpCol = (uint32_t)(warpN * 32) * 2u;

    // softmax addressing: 2 threads per row
    const int srow  = tid >> 1;
    const int shalf = tid & 1;

    // ---- initial work grab ----
    if (tid == 0) *mail = (int)atomicAdd(&g_counter, 1u);
    __syncthreads();
    int w = *mail;                 // unit index (grid 152 <= NUNITS, always valid)
    int tsub = 0;
    int b = w >> 3;                // 8 units per batch
    int mtile = ((w & 7) << 1);    // first tile of unit

    issue_b_full(sB, b, tid);

    // prefetch S for first tile
    float4 sv[16];
    {
        const float4* sp = reinterpret_cast<const float4*>(
            S + (size_t)(b * T_SEQ + mtile * M_TILE + srow) * K_DIM + shalf * 64);
#pragma unroll
        for (int i = 0; i < 16; ++i) sv[i] = sp[i];
    }
    cp_wait<0>();
    __syncthreads();               // B resident

    // ---- persistent tile loop ----
    while (true) {
        const int m0 = mtile * M_TILE;

        // softmax compute from prefetched sv -> packed fp16 rows (in regs)
        uint4 arows[8];
        {
            float4 e[16];
            float sum = 0.f;
#pragma unroll
            for (int i = 0; i < 16; ++i) {
                e[i].x = __expf(sv[i].x); e[i].y = __expf(sv[i].y);
                e[i].z = __expf(sv[i].z); e[i].w = __expf(sv[i].w);
                sum += (e[i].x + e[i].y) + (e[i].z + e[i].w);
            }
            sum += __shfl_xor_sync(0xffffffffu, sum, 1);
            const float inv = 1.0f / sum;
#pragma unroll
            for (int i = 0; i < 8; ++i) {
                arows[i].x = pack_f16x2(e[2 * i].x * inv,     e[2 * i].y * inv);
                arows[i].y = pack_f16x2(e[2 * i].z * inv,     e[2 * i].w * inv);
                arows[i].z = pack_f16x2(e[2 * i + 1].x * inv, e[2 * i + 1].y * inv);
                arows[i].w = pack_f16x2(e[2 * i + 1].z * inv, e[2 * i + 1].w * inv);
            }
        }

        // resolve next work item (grab on last tile of unit)
        const bool grab = (tsub == UNIT_TILES - 1);
        if (grab && tid == 0) *mail = (int)atomicAdd(&g_counter, 1u);

        __syncthreads();           // prev mainloop done reading A; mail visible

        // store A
        {
            char* arow = smem + (size_t)srow * A_PITCH_B + shalf * 128;
#pragma unroll
            for (int i = 0; i < 8; ++i)
                *reinterpret_cast<uint4*>(arow + i * 16) = arows[i];
        }

        int nw = w, ntsub = tsub + 1;
        if (grab) { nw = *mail; ntsub = 0; }
        const bool nhave = (nw < NUNITS);
        const int  nb    = nw >> 3;
        const int  nmtile = ((nw & 7) << 1) + ntsub;

        // prefetch S for next tile (lands during mainloop)
        if (nhave) {
            const float4* sp = reinterpret_cast<const float4*>(
                S + (size_t)(nb * T_SEQ + nmtile * M_TILE + srow) * K_DIM + shalf * 64);
#pragma unroll
            for (int i = 0; i < 16; ++i) sv[i] = sp[i];
        }

        cp_wait<0>();              // any pending B fill landed (per-thread)
        __syncthreads();           // A visible (+ B fill visible)

        // ---- mainloop: 4 N-chunks over resident B, barrier-free ----
        float* outBase = Out + (size_t)(b * T_SEQ + m0) * N_DIM;
#pragma unroll 1
        for (int c = 0; c < NCHUNKS; ++c) {
            const uint32_t bChunk = sB + bLaneOff + bWarpCol + (uint32_t)(c * NCHUNK) * 2u;

            float acc[4][4][4];
#pragma unroll
            for (int mf = 0; mf < 4; ++mf)
#pragma unroll
                for (int nf = 0; nf < 4; ++nf)
#pragma unroll
                    for (int r = 0; r < 4; ++r) acc[mf][nf][r] = 0.f;

#pragma unroll
            for (int s = 0; s < 8; ++s) {
                uint32_t a[4][4];
#pragma unroll
                for (int mf = 0; mf < 4; ++mf)
                    ldsm_x4(a[mf][0], a[mf][1], a[mf][2], a[mf][3],
                            aAddr[mf] + (uint32_t)s * 32u);
                uint32_t bf[2][4];
#pragma unroll
                for (int np = 0; np < 2; ++np)
                    ldsm_x4_trans(bf[np][0], bf[np][1], bf[np][2], bf[np][3],
                                  bChunk + (uint32_t)(np * 16) * 2u
                                         + (uint32_t)s * (16u * B_PITCH_B));
#pragma unroll
                for (int mf = 0; mf < 4; ++mf)
#pragma unroll
                    for (int nf = 0; nf < 4; ++nf)
                        mma_f16(acc[mf][nf][0], acc[mf][nf][1],
                                acc[mf][nf][2], acc[mf][nf][3],
                                a[mf][0], a[mf][1], a[mf][2], a[mf][3],
                                bf[nf >> 1][2 * (nf & 1)], bf[nf >> 1][2 * (nf & 1) + 1]);
            }

            // epilogue: stream accumulators to GMEM
            const int colBase = c * NCHUNK + warpN * 32 + 2 * (lane & 3);
            const int rowBase = warpM * 64 + (lane >> 2);
#pragma unroll
            for (int mf = 0; mf < 4; ++mf) {
                const int r0 = rowBase + mf * 16;
#pragma unroll
                for (int nf = 0; nf < 4; ++nf) {
                    const int col = colBase + nf * 8;
                    float2 v0 = make_float2(acc[mf][nf][0], acc[mf][nf][1]);
                    float2 v1 = make_float2(acc[mf][nf][2], acc[mf][nf][3]);
                    __stcs(reinterpret_cast<float2*>(outBase + (size_t)r0 * N_DIM + col), v0);
                    __stcs(reinterpret_cast<float2*>(outBase + (size_t)(r0 + 8) * N_DIM + col), v1);
                }
            }
        }

        if (!nhave) break;

        if (nb != b) {
            __syncthreads();       // all warps done reading B
            issue_b_full(sB, nb, tid);   // waited at next iteration's cp_wait<0>
        }

        w = nw; tsub = ntsub; b = nb; mtile = nmtile;
    }
}

extern "C" void kernel_launch(void* const* d_in, const int* in_sizes, int n_in,
                              void* d_out, int out_size)
{
    const float* U = (const float*)d_in[0];
    const float* S = (const float*)d_in[1];
    // Robustness: U has 8.4M elements, S has 33.5M. Swap if order differs.
    if (n_in >= 2 && in_sizes[0] == B_BATCH * T_SEQ * K_DIM) {
        const float* t = U; U = S; S = t;
    }
    float* Out = (float*)d_out;

    static int attr_set = 0;
    if (!attr_set) {
        cudaFuncSetAttribute(C2Q_15032385536516_kernel,
                             cudaFuncAttributeMaxDynamicSharedMemorySize, SMEM_TOTAL);
        attr_set = 1;
    }

    // 1) convert U fp32 -> fp16 scratch + reset work counter
    const int n_f4 = B_BATCH * K_DIM * N_DIM / 4;      // 2,097,152
    convert_U_kernel<<<n_f4 / 256, 256>>>(U);

    // 2) persistent fused softmax-GEMM
    C2Q_15032385536516_kernel<<<GRID_MAIN, THREADS, SMEM_TOTAL>>>(S, Out);
}